// round 4
// baseline (speedup 1.0000x reference)
#include <cuda_runtime.h>

#define NB 2
#define NA 100000
#define NC 80
#define NCLS 79          // classes excluding background (class 0)
#define KPERF 500
#define KPROP 100
#define NTASK (NB*NCLS)  // 158
#define SCORE_THR 0.05f
#define THR0 0.99f       // static candidate threshold (self-checked; fallback if violated)
#define CAP 2048         // per-class candidate capacity
#define NSLAB 74
#define CHUNK 1352       // ceil(NA/NSLAB)
#define KEEPC 128        // kept entries per class forwarded to final

typedef unsigned long long u64;
typedef unsigned int u32;

// ---- scratch (static device arrays; allocation-free) ----
__device__ float4 g_boxesDec[NB*NA];
__device__ int    g_cnt[NTASK];
__device__ u64    g_cand[(size_t)NTASK*CAP];   // 2.6 MB
__device__ float  g_fval[NTASK*KEEPC];
__device__ int    g_fflat[NTASK*KEEPC];
__device__ int    g_faidx[NTASK*KEEPC];

__device__ __forceinline__ u32 fmono(float f){
    u32 u = __float_as_uint(f);
    return (u & 0x80000000u) ? ~u : (u | 0x80000000u);
}
__device__ __forceinline__ float fmono_inv(u32 k){
    return __uint_as_float((k & 0x80000000u) ? (k & 0x7FFFFFFFu) : ~k);
}

// ---------------------------------------------------------------- decode boxes (+ zero counters)
__global__ void decode_kernel(const float* __restrict__ bbox,
                              const float* __restrict__ anchors){
    int i = blockIdx.x*blockDim.x + threadIdx.x;
    if (i < NTASK) g_cnt[i] = 0;
    if (i >= NB*NA) return;
    int a = i % NA;
    float4 d  = reinterpret_cast<const float4*>(bbox)[i];
    float4 an = reinterpret_cast<const float4*>(anchors)[a];
    const float MAXR = 4.135166556742356f;   // |ln(16/1000)|
    float dw = fminf(fmaxf(d.z, -MAXR), MAXR);
    float dh = fminf(fmaxf(d.w, -MAXR), MAXR);
    float pw = an.z - an.x, ph = an.w - an.y;
    float px = (an.x + an.z)*0.5f, py = (an.y + an.w)*0.5f;
    float gw = pw*expf(dw), gh = ph*expf(dh);
    float gx = px + pw*d.x, gy = py + ph*d.y;
    float4 o;
    o.x = fminf(fmaxf(gx - gw*0.5f, 0.f), 1.f);
    o.y = fminf(fmaxf(gy - gh*0.5f, 0.f), 1.f);
    o.z = fminf(fmaxf(gx + gw*0.5f, 0.f), 1.f);
    o.w = fminf(fmaxf(gy + gh*0.5f, 0.f), 1.f);
    g_boxesDec[i] = o;
}

// ---------------------------------------------------------------- single fused pass: collect candidates > THR0
// 640 = 32 anchors x 20 float4-lanes; each thread owns a fixed class quartet.
__global__ __launch_bounds__(640) void collect_kernel(const float* __restrict__ y){
    int tid = threadIdx.x;
    int b = blockIdx.y, s = blockIdx.x;
    int p  = tid % 20;
    int c0 = p*4;
    int t0 = b*NCLS + (c0-1), t1 = b*NCLS + c0, t2 = b*NCLS + c0+1, t3 = b*NCLS + c0+2;

    int a0 = s*CHUNK;
    int aN = min(CHUNK, NA - a0);
    const float4* base = reinterpret_cast<const float4*>(y + ((size_t)b*NA + a0)*NC);
    int arow = tid / 20;
    int nf4 = aN*20;
    int k = 0;
    for (int j = tid; j < nf4; j += 640, k++){
        float4 v = base[j];
        u32 a = (u32)(a0 + arow + k*32);
        u64 alo = (u64)(0xFFFFFFFFu - a);
        if (c0 != 0 && v.x > THR0){
            int pos = atomicAdd(&g_cnt[t0], 1);
            if (pos < CAP) g_cand[(size_t)t0*CAP + pos] = ((u64)fmono(v.x) << 32) | alo;
        }
        if (v.y > THR0){
            int pos = atomicAdd(&g_cnt[t1], 1);
            if (pos < CAP) g_cand[(size_t)t1*CAP + pos] = ((u64)fmono(v.y) << 32) | alo;
        }
        if (v.z > THR0){
            int pos = atomicAdd(&g_cnt[t2], 1);
            if (pos < CAP) g_cand[(size_t)t2*CAP + pos] = ((u64)fmono(v.z) << 32) | alo;
        }
        if (v.w > THR0){
            int pos = atomicAdd(&g_cnt[t3], 1);
            if (pos < CAP) g_cand[(size_t)t3*CAP + pos] = ((u64)fmono(v.w) << 32) | alo;
        }
    }
}

// ---------------------------------------------------------------- bitonic (descending), n = pow2
__device__ void bitonic_sort_desc(u64* d, int n){
    int tid = threadIdx.x, nt = blockDim.x;
    for (int k = 2; k <= n; k <<= 1)
        for (int j = k >> 1; j > 0; j >>= 1){
            for (int i = tid; i < n; i += nt){
                int ixj = i ^ j;
                if (ixj > i){
                    u64 a = d[i], b = d[ixj];
                    bool descRegion = ((i & k) == 0);
                    if (descRegion ? (a < b) : (a > b)){ d[i] = b; d[ixj] = a; }
                }
            }
            __syncthreads();
        }
}

// ---------------------------------------------------------------- shared NMS core:
// sbuf[0..n2) initialized (keys desc-sortable); sorts, extracts top-500,
// builds transposed suppression masks, resolves greedy NMS via antitone
// fixed-point (any fixed point == greedy; convergence certified), then
// compacts first KEEPC kept entries to globals.
__device__ void nms_core(int t, int b, int clsr, int n2,
                         u64* sbuf, u32* masksT,
                         float4* sboxes, float* svals, int* saidx,
                         u32* keptw, int* wpref){
    int tid = threadIdx.x;
    __syncthreads();
    bitonic_sort_desc(sbuf, n2);

    bool valid = false;
    if (tid < KPERF){
        u64 key = sbuf[tid];
        u32 mk = (u32)(key >> 32);
        if (mk > 0x80000000u){
            float v = fmono_inv(mk);
            int a = (int)(0xFFFFFFFFu - (u32)key);
            svals[tid] = v; saidx[tid] = a;
            sboxes[tid] = g_boxesDec[b*NA + a];
            valid = (v > 0.0f);
        } else { svals[tid] = -1.0f; saidx[tid] = 0; }
    }
    __syncthreads();   // sbuf reads done; arena may be reused as masksT

    // ---- transposed suppression masks: masksT[i][w] = bits of j<i with IOU(i,j)>0.5
    if (tid < KPERF){
        float4 bi = sboxes[tid];
        float areai = (bi.z - bi.x)*(bi.w - bi.y);
        int w0 = tid >> 5, lane = tid & 31;
        for (int w = 0; w < 16; w++){
            u32 bits = 0;
            if (w <= w0){
                int jbase = w*32;
                int jmax = (w == w0) ? lane : 32;
                for (int j2 = 0; j2 < jmax; j2++){
                    float4 bj = sboxes[jbase + j2];
                    float lx = fmaxf(bi.x, bj.x), ly = fmaxf(bi.y, bj.y);
                    float rx = fminf(bi.z, bj.z), ry = fminf(bi.w, bj.w);
                    float iw = fmaxf(rx - lx, 0.f), ih = fmaxf(ry - ly, 0.f);
                    float inter = iw*ih;
                    float uni = areai + (bj.z - bj.x)*(bj.w - bj.y) - inter;
                    float iou = inter / fmaxf(uni, 1e-9f);
                    if (iou > 0.5f) bits |= (1u << j2);
                }
            }
            masksT[tid*16 + w] = bits;
        }
    }
    // init kept = valid
    {
        u32 bal = __ballot_sync(0xFFFFFFFFu, valid);
        if ((tid & 31) == 0) keptw[tid >> 5] = bal;
    }
    __syncthreads();

    // ---- antitone fixed point (Gauss-Seidel in place; exit certifies K = f(K) = greedy)
    bool converged = false;
    for (int it = 0; it < 16; it++){
        bool supp = false;
        if (tid < KPERF){
            int w0 = tid >> 5;
            const u32* row = masksT + tid*16;
            for (int w = 0; w <= w0; w++) supp |= (keptw[w] & row[w]) != 0u;
        }
        bool nk = valid && !supp;
        u32 nb = __ballot_sync(0xFFFFFFFFu, nk);
        int ch = 0;
        if ((tid & 31) == 0 && nb != keptw[tid >> 5]){ keptw[tid >> 5] = nb; ch = 1; }
        if (__syncthreads_or(ch) == 0){ converged = true; break; }
    }
    if (!converged){
        // exact serial backstop (warp 0)
        if (tid < 32){
            u32 kw = 0;
            for (int i = 0; i < KPERF; i++){
                u32 m = (tid < 16) ? masksT[i*16 + tid] : 0u;
                bool supp = __any_sync(0xFFFFFFFFu, (m & kw) != 0u);
                bool vi = svals[i] > 0.0f;
                if (vi && !supp && tid == (i >> 5)) kw |= 1u << (i & 31);
            }
            if (tid < 16) keptw[tid] = kw;
        }
        __syncthreads();
    }

    if (tid == 0){
        int acc = 0;
        #pragma unroll
        for (int w = 0; w < 16; w++){ wpref[w] = acc; acc += __popc(keptw[w]); }
    }
    __syncthreads();

    if (tid < KPERF){
        int w = tid >> 5, b2 = tid & 31;
        if ((keptw[w] >> b2) & 1u){
            int rank = wpref[w] + __popc(keptw[w] & ((1u << b2) - 1u));
            if (rank < KEEPC){
                g_fval [t*KEEPC + rank] = svals[tid];
                g_fflat[t*KEEPC + rank] = clsr*KPERF + tid;
                g_faidx[t*KEEPC + rank] = saidx[tid];
            }
        }
    }
}

// ---------------------------------------------------------------- per (image,class): fast path
__global__ __launch_bounds__(512) void nms_kernel(){
    __shared__ __align__(16) unsigned char arena[32768];  // sbuf(16KB) -> masksT(32KB)
    u64* sbuf   = (u64*)arena;    // 2048
    u32* masksT = (u32*)arena;    // 500*16
    __shared__ float4 sboxes[KPERF];
    __shared__ float  svals[KPERF];
    __shared__ int    saidx[KPERF];
    __shared__ u32 keptw[16];
    __shared__ int wpref[16];

    int tid = threadIdx.x;
    int t = blockIdx.x;
    int b = t / NCLS, clsr = t % NCLS;

    for (int kk = tid; kk < KEEPC; kk += 512) g_fval[t*KEEPC + kk] = -1.0f;

    int n = g_cnt[t];
    if (n < KPERF || n > CAP) return;   // self-check failed -> fallback kernel handles
    int n2 = 512;
    while (n2 < n) n2 <<= 1;
    for (int i = tid; i < n2; i += 512)
        sbuf[i] = (i < n) ? g_cand[(size_t)t*CAP + i] : 0ull;

    nms_core(t, b, clsr, n2, sbuf, masksT, sboxes, svals, saidx, keptw, wpref);
}

// ---------------------------------------------------------------- cutoff helper (4096 bins, 512 thr)
__device__ void find_cutoff_4096(int* hist, int* part, int K, int* c_out){
    int tid = threadIdx.x;
    int p = 0;
    #pragma unroll
    for (int k = 0; k < 8; k++) p += hist[tid*8 + k];
    part[tid] = p;
    __syncthreads();
    for (int off = 1; off < 512; off <<= 1){
        int v = part[tid];
        if (tid + off < 512) v += part[tid + off];
        __syncthreads();
        part[tid] = v;
        __syncthreads();
    }
    if (tid == 0 && part[0] < K) *c_out = 0;
    if (part[tid] >= K && (tid == 511 || part[tid+1] < K)){
        int cum = (tid == 511) ? 0 : part[tid+1];
        for (int bn = tid*8 + 7; bn >= tid*8; bn--){
            cum += hist[bn];
            if (cum >= K){ *c_out = bn; break; }
        }
    }
    __syncthreads();
}

// ---------------------------------------------------------------- fallback: exact recompute for flagged classes
__global__ __launch_bounds__(512) void fallback_kernel(const float* __restrict__ y){
    __shared__ __align__(16) unsigned char arena[32768]; // hist+part -> sbuf -> masksT
    __shared__ float4 sboxes[KPERF];
    __shared__ float  svals[KPERF];
    __shared__ int    saidx[KPERF];
    __shared__ u32 keptw[16];
    __shared__ int wpref[16];
    __shared__ int sc1, scnt;

    int tid = threadIdx.x;
    int t = blockIdx.x;
    int n = g_cnt[t];
    if (n >= KPERF && n <= CAP) return;      // fast path already handled it

    int b = t / NCLS, clsr = t % NCLS;
    int c = clsr + 1;
    const float* col = y + (size_t)b*NA*NC + c;

    int* hist = (int*)arena;                 // 4096
    int* part = (int*)(arena + 16384);       // 512
    for (int i = tid; i < 4096; i += 512) hist[i] = 0;
    __syncthreads();
    for (int a = tid; a < NA; a += 512){
        float v = col[(size_t)a*NC];
        if (v > SCORE_THR){
            int bn = (int)(v*4096.f); bn = bn > 4095 ? 4095 : bn;
            atomicAdd(&hist[bn], 1);
        }
    }
    __syncthreads();
    find_cutoff_4096(hist, part, KPERF, &sc1);
    int c1 = sc1;
    if (tid == 0) scnt = 0;
    __syncthreads();                         // hist no longer needed

    u64* sbuf = (u64*)arena;                 // reuse arena (c1 saved in register)
    for (int a = tid; a < NA; a += 512){
        float v = col[(size_t)a*NC];
        if (v > SCORE_THR){
            int bn = (int)(v*4096.f); bn = bn > 4095 ? 4095 : bn;
            if (bn >= c1){
                int pos = atomicAdd(&scnt, 1);
                if (pos < CAP)
                    sbuf[pos] = ((u64)fmono(v) << 32) | (u64)(0xFFFFFFFFu - (u32)a);
            }
        }
    }
    __syncthreads();
    int m = min(scnt, CAP);
    int n2 = 512;
    while (n2 < m) n2 <<= 1;
    for (int i = m + tid; i < n2; i += 512) sbuf[i] = 0ull;

    nms_core(t, b, clsr, n2, sbuf, (u32*)arena, sboxes, svals, saidx, keptw, wpref);
}

// ---------------------------------------------------------------- per image: global top-100 + gather
__global__ __launch_bounds__(512) void final_kernel(const float* __restrict__ y_pred,
                                                    float* __restrict__ out){
    __shared__ int hist[4096];
    __shared__ int part[512];
    __shared__ u64 skey[512];
    __shared__ int sc1, sab1, sc2, sab2, scnt;
    __shared__ int sA[KPROP];
    int tid = threadIdx.x;
    int b = blockIdx.x;
    const int M = NCLS*KEEPC;                  // 10112
    const int gbase = b*M;

    // ---- level-1 cutoff
    for (int i = tid; i < 4096; i += 512) hist[i] = 0;
    __syncthreads();
    for (int i = tid; i < M; i += 512){
        float v = g_fval[gbase + i];
        if (v > 0.f){
            int bn = (int)(v*4096.f); bn = bn > 4095 ? 4095 : bn;
            atomicAdd(&hist[bn], 1);
        }
    }
    __syncthreads();
    // suffix-scan with above-count
    {
        int p = 0;
        #pragma unroll
        for (int k = 0; k < 8; k++) p += hist[tid*8 + k];
        part[tid] = p;
        __syncthreads();
        for (int off = 1; off < 512; off <<= 1){
            int v = part[tid];
            if (tid + off < 512) v += part[tid + off];
            __syncthreads();
            part[tid] = v;
            __syncthreads();
        }
        if (tid == 0 && part[0] < KPROP){ sc1 = 0; sab1 = 0; }
        if (part[tid] >= KPROP && (tid == 511 || part[tid+1] < KPROP)){
            int cum = (tid == 511) ? 0 : part[tid+1];
            for (int bn = tid*8 + 7; bn >= tid*8; bn--){
                cum += hist[bn];
                if (cum >= KPROP){ sc1 = bn; sab1 = cum - hist[bn]; break; }
            }
        }
        __syncthreads();
    }
    int c1 = sc1, ab1 = sab1;

    // ---- level-2 refinement inside cutoff bin
    for (int i = tid; i < 4096; i += 512) hist[i] = 0;
    __syncthreads();
    for (int i = tid; i < M; i += 512){
        float v = g_fval[gbase + i];
        if (v > 0.f){
            float t1 = v*4096.f;
            int bn = (int)t1; bn = bn > 4095 ? 4095 : bn;
            if (bn == c1){
                float fr = t1 - (float)c1;
                int sub = (int)(fr*4096.f); sub = sub < 0 ? 0 : (sub > 4095 ? 4095 : sub);
                atomicAdd(&hist[sub], 1);
            }
        }
    }
    __syncthreads();
    {
        int K2 = KPROP - ab1;
        int p = 0;
        #pragma unroll
        for (int k = 0; k < 8; k++) p += hist[tid*8 + k];
        part[tid] = p;
        __syncthreads();
        for (int off = 1; off < 512; off <<= 1){
            int v = part[tid];
            if (tid + off < 512) v += part[tid + off];
            __syncthreads();
            part[tid] = v;
            __syncthreads();
        }
        if (tid == 0 && part[0] < K2) sc2 = 0;
        if (part[tid] >= K2 && (tid == 511 || part[tid+1] < K2)){
            int cum = (tid == 511) ? 0 : part[tid+1];
            for (int bn = tid*8 + 7; bn >= tid*8; bn--){
                cum += hist[bn];
                if (cum >= K2){ sc2 = bn; break; }
            }
        }
        __syncthreads();
    }
    int c2 = sc2;

    // ---- gather survivors
    if (tid == 0) scnt = 0;
    __syncthreads();
    for (int i = tid; i < M; i += 512){
        float v = g_fval[gbase + i];
        if (v > 0.f){
            float t1 = v*4096.f;
            int bn = (int)t1; bn = bn > 4095 ? 4095 : bn;
            bool sel = bn > c1;
            if (bn == c1){
                float fr = t1 - (float)c1;
                int sub = (int)(fr*4096.f); sub = sub < 0 ? 0 : (sub > 4095 ? 4095 : sub);
                sel = (sub >= c2);
            }
            if (sel){
                int pos = atomicAdd(&scnt, 1);
                if (pos < 512){
                    u32 fflat = (u32)g_fflat[gbase + i];
                    skey[pos] = ((u64)fmono(v) << 32) | ((u64)(65535u - fflat) << 14) | (u64)i;
                }
            }
        }
    }
    __syncthreads();
    int n = min(scnt, 512);
    for (int i = n + tid; i < 512; i += 512) skey[i] = 0ull;
    __syncthreads();
    bitonic_sort_desc(skey, 512);

    if (tid < KPROP){
        u64 key = skey[tid];
        u32 mk = (u32)(key >> 32);
        if (mk > 0x80000000u){
            int slot = (int)(key & 0x3FFFull);
            sA[tid] = g_faidx[gbase + slot];
        } else sA[tid] = -1;
    }
    __syncthreads();

    float* oscores = out;                         // [B,PROP,C]
    float* oboxes  = out + NB*KPROP*NC;           // [B,PROP,4]
    for (int idx = tid; idx < KPROP*NC; idx += 512){
        int p = idx / NC, cc = idx % NC;
        int a = sA[p];
        oscores[(b*KPROP + p)*NC + cc] = (a >= 0) ? y_pred[((size_t)b*NA + a)*NC + cc] : 0.f;
    }
    if (tid < KPROP){
        int a = sA[tid];
        float4 bx = (a >= 0) ? g_boxesDec[b*NA + a] : make_float4(0.f, 0.f, 0.f, 0.f);
        reinterpret_cast<float4*>(oboxes)[b*KPROP + tid] = bx;
    }
}

// ----------------------------------------------------------------
extern "C" void kernel_launch(void* const* d_in, const int* in_sizes, int n_in,
                              void* d_out, int out_size){
    (void)in_sizes; (void)n_in; (void)out_size;
    const float* y    = (const float*)d_in[0];   // [B,A,C]
    const float* bbox = (const float*)d_in[1];   // [B,A,4]
    const float* anch = (const float*)d_in[2];   // [A,4]
    float* out = (float*)d_out;

    decode_kernel<<<(NB*NA + 255)/256, 256>>>(bbox, anch);
    collect_kernel<<<dim3(NSLAB, NB), 640>>>(y);
    nms_kernel<<<NTASK, 512>>>();
    fallback_kernel<<<NTASK, 512>>>(y);
    final_kernel<<<NB, 512>>>(y, out);
}

// round 5
// speedup vs baseline: 1.0381x; 1.0381x over previous
#include <cuda_runtime.h>

#define NB 2
#define NA 100000
#define NC 80
#define NCLS 79          // classes excluding background (class 0)
#define KPERF 500
#define KPROP 100
#define NTASK (NB*NCLS)  // 158
#define SCORE_THR 0.05f
#define THR0 0.99f       // static candidate threshold (self-checked; in-kernel fallback if violated)
#define CAP 2048         // per-class candidate capacity
#define NSLAB 74
#define CHUNK 1352       // ceil(NA/NSLAB)
#define KEEPC 128        // kept entries per class forwarded to final
#define MFIN (NCLS*KEEPC)   // 10112
#define RPT 20           // ceil(MFIN/512)

typedef unsigned long long u64;
typedef unsigned int u32;

// ---- scratch (static device arrays; allocation-free; zero-init at module load) ----
__device__ float4 g_boxesDec[NB*NA];
__device__ int    g_cnt[NTASK];
__device__ u64    g_cand[(size_t)NTASK*CAP];   // 2.6 MB
__device__ float  g_fval[NTASK*KEEPC];
__device__ int    g_fflat[NTASK*KEEPC];
__device__ int    g_faidx[NTASK*KEEPC];

__device__ __forceinline__ u32 fmono(float f){
    u32 u = __float_as_uint(f);
    return (u & 0x80000000u) ? ~u : (u | 0x80000000u);
}
__device__ __forceinline__ float fmono_inv(u32 k){
    return __uint_as_float((k & 0x80000000u) ? (k & 0x7FFFFFFFu) : ~k);
}

// ================================================================ kernel 1: decode + collect (fused)
__global__ __launch_bounds__(640) void fused_kernel(const float* __restrict__ y,
                                                    const float* __restrict__ bbox,
                                                    const float* __restrict__ anch){
    int tid = threadIdx.x;
    int b = blockIdx.y, s = blockIdx.x;
    int a0 = s*CHUNK;
    int aN = min(CHUNK, NA - a0);

    // ---- decode this block's anchor chunk
    const float MAXR = 4.135166556742356f;   // |ln(16/1000)|
    for (int i = tid; i < aN; i += 640){
        int a = a0 + i;
        float4 d  = reinterpret_cast<const float4*>(bbox)[b*NA + a];
        float4 an = reinterpret_cast<const float4*>(anch)[a];
        float dw = fminf(fmaxf(d.z, -MAXR), MAXR);
        float dh = fminf(fmaxf(d.w, -MAXR), MAXR);
        float pw = an.z - an.x, ph = an.w - an.y;
        float px = (an.x + an.z)*0.5f, py = (an.y + an.w)*0.5f;
        float gw = pw*expf(dw), gh = ph*expf(dh);
        float gx = px + pw*d.x, gy = py + ph*d.y;
        float4 o;
        o.x = fminf(fmaxf(gx - gw*0.5f, 0.f), 1.f);
        o.y = fminf(fmaxf(gy - gh*0.5f, 0.f), 1.f);
        o.z = fminf(fmaxf(gx + gw*0.5f, 0.f), 1.f);
        o.w = fminf(fmaxf(gy + gh*0.5f, 0.f), 1.f);
        g_boxesDec[b*NA + a] = o;
    }

    // ---- collect candidates > THR0 (thread owns a fixed class quartet)
    int p  = tid % 20;
    int c0 = p*4;
    int t0 = b*NCLS + (c0-1), t1 = b*NCLS + c0, t2 = b*NCLS + c0+1, t3 = b*NCLS + c0+2;
    const float4* base = reinterpret_cast<const float4*>(y + ((size_t)b*NA + a0)*NC);
    int arow = tid / 20;
    int nf4 = aN*20;
    int k = 0;
    for (int j = tid; j < nf4; j += 640, k++){
        float4 v = base[j];
        u32 a = (u32)(a0 + arow + k*32);
        u64 alo = (u64)(0xFFFFFFFFu - a);
        if (c0 != 0 && v.x > THR0){
            int pos = atomicAdd(&g_cnt[t0], 1);
            if (pos < CAP) g_cand[(size_t)t0*CAP + pos] = ((u64)fmono(v.x) << 32) | alo;
        }
        if (v.y > THR0){
            int pos = atomicAdd(&g_cnt[t1], 1);
            if (pos < CAP) g_cand[(size_t)t1*CAP + pos] = ((u64)fmono(v.y) << 32) | alo;
        }
        if (v.z > THR0){
            int pos = atomicAdd(&g_cnt[t2], 1);
            if (pos < CAP) g_cand[(size_t)t2*CAP + pos] = ((u64)fmono(v.z) << 32) | alo;
        }
        if (v.w > THR0){
            int pos = atomicAdd(&g_cnt[t3], 1);
            if (pos < CAP) g_cand[(size_t)t3*CAP + pos] = ((u64)fmono(v.w) << 32) | alo;
        }
    }
}

// ---------------------------------------------------------------- bitonic (descending), n = pow2
__device__ void bitonic_sort_desc(u64* d, int n){
    int tid = threadIdx.x, nt = blockDim.x;
    for (int k = 2; k <= n; k <<= 1)
        for (int j = k >> 1; j > 0; j >>= 1){
            for (int i = tid; i < n; i += nt){
                int ixj = i ^ j;
                if (ixj > i){
                    u64 a = d[i], b = d[ixj];
                    bool descRegion = ((i & k) == 0);
                    if (descRegion ? (a < b) : (a > b)){ d[i] = b; d[ixj] = a; }
                }
            }
            __syncthreads();
        }
}

// ---------------------------------------------------------------- NMS core (shared by fast + fallback paths)
__device__ void nms_core(int t, int b, int clsr, int n2,
                         u64* sbuf, u32* masksT,
                         float4* sboxes, float* svals, int* saidx,
                         u32* keptw, int* wpref){
    int tid = threadIdx.x;
    __syncthreads();
    bitonic_sort_desc(sbuf, n2);

    bool valid = false;
    if (tid < KPERF){
        u64 key = sbuf[tid];
        u32 mk = (u32)(key >> 32);
        if (mk > 0x80000000u){
            float v = fmono_inv(mk);
            int a = (int)(0xFFFFFFFFu - (u32)key);
            svals[tid] = v; saidx[tid] = a;
            sboxes[tid] = g_boxesDec[b*NA + a];
            valid = (v > 0.0f);
        } else { svals[tid] = -1.0f; saidx[tid] = 0; }
    }
    __syncthreads();   // sbuf reads done; arena may be reused as masksT

    // transposed suppression masks: masksT[i][w] = bits of j<i with IOU(i,j)>0.5
    if (tid < KPERF){
        float4 bi = sboxes[tid];
        float areai = (bi.z - bi.x)*(bi.w - bi.y);
        int w0 = tid >> 5, lane = tid & 31;
        for (int w = 0; w < 16; w++){
            u32 bits = 0;
            if (w <= w0){
                int jbase = w*32;
                int jmax = (w == w0) ? lane : 32;
                for (int j2 = 0; j2 < jmax; j2++){
                    float4 bj = sboxes[jbase + j2];
                    float lx = fmaxf(bi.x, bj.x), ly = fmaxf(bi.y, bj.y);
                    float rx = fminf(bi.z, bj.z), ry = fminf(bi.w, bj.w);
                    float iw = fmaxf(rx - lx, 0.f), ih = fmaxf(ry - ly, 0.f);
                    float inter = iw*ih;
                    float uni = areai + (bj.z - bj.x)*(bj.w - bj.y) - inter;
                    float iou = inter / fmaxf(uni, 1e-9f);
                    if (iou > 0.5f) bits |= (1u << j2);
                }
            }
            masksT[tid*16 + w] = bits;
        }
    }
    {
        u32 bal = __ballot_sync(0xFFFFFFFFu, valid);
        if ((tid & 31) == 0) keptw[tid >> 5] = bal;
    }
    __syncthreads();

    // antitone fixed point (any fixed point == greedy NMS; convergence certified)
    bool converged = false;
    for (int it = 0; it < 16; it++){
        bool supp = false;
        if (tid < KPERF){
            int w0 = tid >> 5;
            const u32* row = masksT + tid*16;
            for (int w = 0; w <= w0; w++) supp |= (keptw[w] & row[w]) != 0u;
        }
        bool nk = valid && !supp;
        u32 nb = __ballot_sync(0xFFFFFFFFu, nk);
        int ch = 0;
        if ((tid & 31) == 0 && nb != keptw[tid >> 5]){ keptw[tid >> 5] = nb; ch = 1; }
        if (__syncthreads_or(ch) == 0){ converged = true; break; }
    }
    if (!converged){
        if (tid < 32){       // exact serial backstop
            u32 kw = 0;
            for (int i = 0; i < KPERF; i++){
                u32 m = (tid < 16) ? masksT[i*16 + tid] : 0u;
                bool supp = __any_sync(0xFFFFFFFFu, (m & kw) != 0u);
                bool vi = svals[i] > 0.0f;
                if (vi && !supp && tid == (i >> 5)) kw |= 1u << (i & 31);
            }
            if (tid < 16) keptw[tid] = kw;
        }
        __syncthreads();
    }

    if (tid == 0){
        int acc = 0;
        #pragma unroll
        for (int w = 0; w < 16; w++){ wpref[w] = acc; acc += __popc(keptw[w]); }
    }
    __syncthreads();

    if (tid < KPERF){
        int w = tid >> 5, b2 = tid & 31;
        if ((keptw[w] >> b2) & 1u){
            int rank = wpref[w] + __popc(keptw[w] & ((1u << b2) - 1u));
            if (rank < KEEPC){
                g_fval [t*KEEPC + rank] = svals[tid];
                g_fflat[t*KEEPC + rank] = clsr*KPERF + tid;
                g_faidx[t*KEEPC + rank] = saidx[tid];
            }
        }
    }
}

// ---------------------------------------------------------------- cutoff helper for fallback (4096 bins)
__device__ void find_cutoff_4096(int* hist, int* part, int K, int* c_out){
    int tid = threadIdx.x;
    int p = 0;
    #pragma unroll
    for (int k = 0; k < 8; k++) p += hist[tid*8 + k];
    part[tid] = p;
    __syncthreads();
    for (int off = 1; off < 512; off <<= 1){
        int v = part[tid];
        if (tid + off < 512) v += part[tid + off];
        __syncthreads();
        part[tid] = v;
        __syncthreads();
    }
    if (tid == 0 && part[0] < K) *c_out = 0;
    if (part[tid] >= K && (tid == 511 || part[tid+1] < K)){
        int cum = (tid == 511) ? 0 : part[tid+1];
        for (int bn = tid*8 + 7; bn >= tid*8; bn--){
            cum += hist[bn];
            if (cum >= K){ *c_out = bn; break; }
        }
    }
    __syncthreads();
}

// ================================================================ kernel 2: per (image,class) NMS (+fallback)
__global__ __launch_bounds__(512) void nms_kernel(const float* __restrict__ y){
    __shared__ __align__(16) unsigned char arena[32768];  // sbuf/hist -> masksT
    __shared__ float4 sboxes[KPERF];
    __shared__ float  svals[KPERF];
    __shared__ int    saidx[KPERF];
    __shared__ u32 keptw[16];
    __shared__ int wpref[16];
    __shared__ int sn, scnt, sc1;

    int tid = threadIdx.x;
    int t = blockIdx.x;
    int b = t / NCLS, clsr = t % NCLS;

    for (int kk = tid; kk < KEEPC; kk += 512) g_fval[t*KEEPC + kk] = -1.0f;

    if (tid == 0){ sn = g_cnt[t]; g_cnt[t] = 0; }   // read + re-zero for next graph replay
    __syncthreads();
    int n = sn;
    int n2;
    u64* sbuf = (u64*)arena;

    if (n >= KPERF && n <= CAP){
        // ---- fast path: candidates already collected
        n2 = 512;
        while (n2 < n) n2 <<= 1;
        #pragma unroll 4
        for (int i = tid; i < n2; i += 512)
            sbuf[i] = (i < n) ? g_cand[(size_t)t*CAP + i] : 0ull;
    } else {
        // ---- exact fallback: histogram-select from the raw column
        int c = clsr + 1;
        const float* col = y + (size_t)b*NA*NC + c;
        int* hist = (int*)arena;                 // 4096 ints
        int* part = (int*)(arena + 16384);       // 512 ints
        for (int i = tid; i < 4096; i += 512) hist[i] = 0;
        __syncthreads();
        for (int a = tid; a < NA; a += 512){
            float v = col[(size_t)a*NC];
            if (v > SCORE_THR){
                int bn = (int)(v*4096.f); bn = bn > 4095 ? 4095 : bn;
                atomicAdd(&hist[bn], 1);
            }
        }
        __syncthreads();
        find_cutoff_4096(hist, part, KPERF, &sc1);
        int c1 = sc1;
        if (tid == 0) scnt = 0;
        __syncthreads();                         // hist dead; reuse arena as sbuf
        for (int a = tid; a < NA; a += 512){
            float v = col[(size_t)a*NC];
            if (v > SCORE_THR){
                int bn = (int)(v*4096.f); bn = bn > 4095 ? 4095 : bn;
                if (bn >= c1){
                    int pos = atomicAdd(&scnt, 1);
                    if (pos < CAP)
                        sbuf[pos] = ((u64)fmono(v) << 32) | (u64)(0xFFFFFFFFu - (u32)a);
                }
            }
        }
        __syncthreads();
        int m = min(scnt, CAP);
        n2 = 512;
        while (n2 < m) n2 <<= 1;
        for (int i = m + tid; i < n2; i += 512) sbuf[i] = 0ull;
    }

    nms_core(t, b, clsr, n2, sbuf, (u32*)arena, sboxes, svals, saidx, keptw, wpref);
}

// ================================================================ kernel 3: per-image global top-100 + gather
// Values staged once into registers (RPT per thread, unrolled -> full MLP);
// both histogram levels + gather run register-resident.
__global__ __launch_bounds__(512) void final_kernel(const float* __restrict__ y_pred,
                                                    float* __restrict__ out){
    __shared__ int hist[4096];
    __shared__ int wt[16];
    __shared__ int sc, sab, sc2, scnt;
    __shared__ u64 skey[512];
    __shared__ int sA[KPROP];
    int tid = threadIdx.x;
    int lane = tid & 31, wrp = tid >> 5;
    int b = blockIdx.x;
    const int gbase = b*MFIN;

    // ---- stage values into registers (independent loads)
    float vreg[RPT];
    #pragma unroll
    for (int k = 0; k < RPT; k++){
        int idx = tid + k*512;
        vreg[k] = (idx < MFIN) ? g_fval[gbase + idx] : -1.0f;
    }

    // ---- level-1 histogram
    for (int i = tid; i < 4096; i += 512) hist[i] = 0;
    __syncthreads();
    #pragma unroll
    for (int k = 0; k < RPT; k++){
        float v = vreg[k];
        if (v > 0.f){
            int bn = (int)(v*4096.f); bn = bn > 4095 ? 4095 : bn;
            atomicAdd(&hist[bn], 1);
        }
    }
    __syncthreads();

    // ---- level-1 cutoff via warp suffix scan
    {
        int p = 0;
        #pragma unroll
        for (int k = 0; k < 8; k++) p += hist[tid*8 + k];
        int s = p;
        #pragma unroll
        for (int off = 1; off < 32; off <<= 1){
            int v = __shfl_down_sync(0xFFFFFFFFu, s, off);
            if (lane + off < 32) s += v;
        }
        if (lane == 0) wt[wrp] = s;
        __syncthreads();
        int wsuf = 0;
        #pragma unroll
        for (int j = 0; j < 16; j++) if (j > wrp) wsuf += wt[j];
        int St = s + wsuf;            // suffix-sum from this thread's group
        if (tid == 0 && St < KPROP){ sc = 0; sab = 0; }
        if (St >= KPROP && St - p < KPROP){
            int cum = St - p;
            for (int bn = tid*8 + 7; bn >= tid*8; bn--){
                cum += hist[bn];
                if (cum >= KPROP){ sc = bn; sab = cum - hist[bn]; break; }
            }
        }
        __syncthreads();
    }
    int c1 = sc, ab1 = sab;

    // ---- level-2 histogram inside cutoff bin
    for (int i = tid; i < 4096; i += 512) hist[i] = 0;
    __syncthreads();
    #pragma unroll
    for (int k = 0; k < RPT; k++){
        float v = vreg[k];
        if (v > 0.f){
            float t1 = v*4096.f;
            int bn = (int)t1; bn = bn > 4095 ? 4095 : bn;
            if (bn == c1){
                float fr = t1 - (float)c1;
                int sub = (int)(fr*4096.f); sub = sub < 0 ? 0 : (sub > 4095 ? 4095 : sub);
                atomicAdd(&hist[sub], 1);
            }
        }
    }
    __syncthreads();
    {
        int K2 = KPROP - ab1;
        int p = 0;
        #pragma unroll
        for (int k = 0; k < 8; k++) p += hist[tid*8 + k];
        int s = p;
        #pragma unroll
        for (int off = 1; off < 32; off <<= 1){
            int v = __shfl_down_sync(0xFFFFFFFFu, s, off);
            if (lane + off < 32) s += v;
        }
        if (lane == 0) wt[wrp] = s;
        __syncthreads();
        int wsuf = 0;
        #pragma unroll
        for (int j = 0; j < 16; j++) if (j > wrp) wsuf += wt[j];
        int St = s + wsuf;
        if (tid == 0 && St < K2) sc2 = 0;
        if (St >= K2 && St - p < K2){
            int cum = St - p;
            for (int bn = tid*8 + 7; bn >= tid*8; bn--){
                cum += hist[bn];
                if (cum >= K2){ sc2 = bn; break; }
            }
        }
        __syncthreads();
    }
    int c2 = sc2;

    // ---- gather survivors (register-resident test; lazy g_fflat load)
    if (tid == 0) scnt = 0;
    __syncthreads();
    #pragma unroll
    for (int k = 0; k < RPT; k++){
        float v = vreg[k];
        if (v > 0.f){
            float t1 = v*4096.f;
            int bn = (int)t1; bn = bn > 4095 ? 4095 : bn;
            bool sel = bn > c1;
            if (bn == c1){
                float fr = t1 - (float)c1;
                int sub = (int)(fr*4096.f); sub = sub < 0 ? 0 : (sub > 4095 ? 4095 : sub);
                sel = (sub >= c2);
            }
            if (sel){
                int i = tid + k*512;
                int pos = atomicAdd(&scnt, 1);
                if (pos < 512){
                    u32 fflat = (u32)g_fflat[gbase + i];
                    skey[pos] = ((u64)fmono(v) << 32) | ((u64)(65535u - fflat) << 14) | (u64)i;
                }
            }
        }
    }
    __syncthreads();
    int n = min(scnt, 512);
    for (int i = n + tid; i < 512; i += 512) skey[i] = 0ull;
    __syncthreads();
    bitonic_sort_desc(skey, 512);

    if (tid < KPROP){
        u64 key = skey[tid];
        u32 mk = (u32)(key >> 32);
        if (mk > 0x80000000u){
            int slot = (int)(key & 0x3FFFull);
            sA[tid] = g_faidx[gbase + slot];
        } else sA[tid] = -1;
    }
    __syncthreads();

    float* oscores = out;                         // [B,PROP,C]
    float* oboxes  = out + NB*KPROP*NC;           // [B,PROP,4]
    for (int idx = tid; idx < KPROP*NC; idx += 512){
        int p = idx / NC, cc = idx % NC;
        int a = sA[p];
        oscores[(b*KPROP + p)*NC + cc] = (a >= 0) ? y_pred[((size_t)b*NA + a)*NC + cc] : 0.f;
    }
    if (tid < KPROP){
        int a = sA[tid];
        float4 bx = (a >= 0) ? g_boxesDec[b*NA + a] : make_float4(0.f, 0.f, 0.f, 0.f);
        reinterpret_cast<float4*>(oboxes)[b*KPROP + tid] = bx;
    }
}

// ----------------------------------------------------------------
extern "C" void kernel_launch(void* const* d_in, const int* in_sizes, int n_in,
                              void* d_out, int out_size){
    (void)in_sizes; (void)n_in; (void)out_size;
    const float* y    = (const float*)d_in[0];   // [B,A,C]
    const float* bbox = (const float*)d_in[1];   // [B,A,4]
    const float* anch = (const float*)d_in[2];   // [A,4]
    float* out = (float*)d_out;

    fused_kernel<<<dim3(NSLAB, NB), 640>>>(y, bbox, anch);
    nms_kernel<<<NTASK, 512>>>(y);
    final_kernel<<<NB, 512>>>(y, out);
}

// round 6
// speedup vs baseline: 2.0705x; 1.9945x over previous
#include <cuda_runtime.h>

#define NB 2
#define NA 100000
#define NC 80
#define NCLS 79          // classes excluding background (class 0)
#define KPERF 500
#define KPROP 100
#define NTASK (NB*NCLS)  // 158
#define SCORE_THR 0.05f
#define THR0 0.992f      // static candidate threshold (self-checked; in-kernel fallback if violated)
#define CAP 2048         // per-class candidate capacity
#define NSLAB 222
#define CHUNK 451        // 222*451 = 100122 >= NA
#define KEEPC 128        // kept entries per class forwarded to final
#define MFIN (NCLS*KEEPC)   // 10112
#define RPT 20           // ceil(MFIN/512)

typedef unsigned long long u64;
typedef unsigned int u32;

// ---- scratch (static device arrays; allocation-free) ----
__device__ int    g_cnt[NTASK];
__device__ u64    g_cand[(size_t)NTASK*CAP];   // 2.6 MB
__device__ float  g_fval[NTASK*KEEPC];
__device__ int    g_fflat[NTASK*KEEPC];
__device__ int    g_faidx[NTASK*KEEPC];

__device__ __forceinline__ u32 fmono(float f){
    u32 u = __float_as_uint(f);
    return (u & 0x80000000u) ? ~u : (u | 0x80000000u);
}
__device__ __forceinline__ float fmono_inv(u32 k){
    return __uint_as_float((k & 0x80000000u) ? (k & 0x7FFFFFFFu) : ~k);
}

// mmdet delta decode + clip to [0,1]
__device__ __forceinline__ float4 decode_box(float4 d, float4 an){
    const float MAXR = 4.135166556742356f;   // |ln(16/1000)|
    float dw = fminf(fmaxf(d.z, -MAXR), MAXR);
    float dh = fminf(fmaxf(d.w, -MAXR), MAXR);
    float pw = an.z - an.x, ph = an.w - an.y;
    float px = (an.x + an.z)*0.5f, py = (an.y + an.w)*0.5f;
    float gw = pw*expf(dw), gh = ph*expf(dh);
    float gx = px + pw*d.x, gy = py + ph*d.y;
    float4 o;
    o.x = fminf(fmaxf(gx - gw*0.5f, 0.f), 1.f);
    o.y = fminf(fmaxf(gy - gh*0.5f, 0.f), 1.f);
    o.z = fminf(fmaxf(gx + gw*0.5f, 0.f), 1.f);
    o.w = fminf(fmaxf(gy + gh*0.5f, 0.f), 1.f);
    return o;
}

// ================================================================ kernel 1: collect candidates > THR0
// 640 = 32 anchors x 20 float4-lanes; each thread owns a fixed class quartet.
__global__ __launch_bounds__(640) void collect_kernel(const float* __restrict__ y){
    int tid = threadIdx.x;
    int b = blockIdx.y, s = blockIdx.x;
    int a0 = s*CHUNK;
    int aN = min(CHUNK, NA - a0);
    int p  = tid % 20;
    int c0 = p*4;
    int t0 = b*NCLS + (c0-1), t1 = b*NCLS + c0, t2 = b*NCLS + c0+1, t3 = b*NCLS + c0+2;
    const float4* base = reinterpret_cast<const float4*>(y + ((size_t)b*NA + a0)*NC);
    int arow = tid / 20;
    int nf4 = aN*20;
    int k = 0;
    for (int j = tid; j < nf4; j += 640, k++){
        float4 v = base[j];
        u32 a = (u32)(a0 + arow + k*32);
        u64 alo = (u64)(0xFFFFFFFFu - a);
        if (c0 != 0 && v.x > THR0){
            int pos = atomicAdd(&g_cnt[t0], 1);
            if (pos < CAP) g_cand[(size_t)t0*CAP + pos] = ((u64)fmono(v.x) << 32) | alo;
        }
        if (v.y > THR0){
            int pos = atomicAdd(&g_cnt[t1], 1);
            if (pos < CAP) g_cand[(size_t)t1*CAP + pos] = ((u64)fmono(v.y) << 32) | alo;
        }
        if (v.z > THR0){
            int pos = atomicAdd(&g_cnt[t2], 1);
            if (pos < CAP) g_cand[(size_t)t2*CAP + pos] = ((u64)fmono(v.z) << 32) | alo;
        }
        if (v.w > THR0){
            int pos = atomicAdd(&g_cnt[t3], 1);
            if (pos < CAP) g_cand[(size_t)t3*CAP + pos] = ((u64)fmono(v.w) << 32) | alo;
        }
    }
}

// ---------------------------------------------------------------- classic smem bitonic (desc), n = pow2 (fallback path)
__device__ void bitonic_sort_desc(u64* d, int n){
    int tid = threadIdx.x, nt = blockDim.x;
    for (int k = 2; k <= n; k <<= 1)
        for (int j = k >> 1; j > 0; j >>= 1){
            for (int i = tid; i < n; i += nt){
                int ixj = i ^ j;
                if (ixj > i){
                    u64 a = d[i], b = d[ixj];
                    bool descRegion = ((i & k) == 0);
                    if (descRegion ? (a < b) : (a > b)){ d[i] = b; d[ixj] = a; }
                }
            }
            __syncthreads();
        }
}

// ---------------------------------------------------------------- hybrid register/shfl bitonic, n=1024, 512 threads
// 2 elements per thread: e0=E[2t], e1=E[2t+1].  Stages j<=32 run in registers
// (shfl_xor); only j>=64 touch smem.  Result (descending) stored to sm[0..1024).
__device__ __forceinline__ u64 shfl_xor_u64(u64 x, int m){
    u32 lo = (u32)x, hi = (u32)(x >> 32);
    lo = __shfl_xor_sync(0xFFFFFFFFu, lo, m);
    hi = __shfl_xor_sync(0xFFFFFFFFu, hi, m);
    return ((u64)hi << 32) | lo;
}
__device__ void hybrid_sort_1024(u64* sm, u64 e0, u64 e1){
    int t = threadIdx.x;
    #pragma unroll
    for (int k = 2; k <= 1024; k <<= 1){
        bool desc = (((2*t) & k) == 0);
        for (int j = k >> 1; j >= 64; j >>= 1){
            sm[2*t] = e0; sm[2*t+1] = e1;
            __syncthreads();
            u64 o0 = sm[(2*t) ^ j], o1 = sm[(2*t+1) ^ j];
            bool lower = ((t & (j >> 1)) == 0);
            bool keepmax = (desc == lower);
            e0 = (keepmax == (e0 > o0)) ? e0 : o0;
            e1 = (keepmax == (e1 > o1)) ? e1 : o1;
            __syncthreads();
        }
        #pragma unroll
        for (int j = 32; j >= 2; j >>= 1){
            if (j <= (k >> 1)){
                int lm = j >> 1;
                u64 o0 = shfl_xor_u64(e0, lm);
                u64 o1 = shfl_xor_u64(e1, lm);
                bool lower = ((t & lm) == 0);
                bool keepmax = (desc == lower);
                e0 = (keepmax == (e0 > o0)) ? e0 : o0;
                e1 = (keepmax == (e1 > o1)) ? e1 : o1;
            }
        }
        {   // j == 1: in-thread (index 2t is the lower)
            u64 a = e0, b = e1;
            u64 mx = a > b ? a : b, mn = a > b ? b : a;
            e0 = desc ? mx : mn;
            e1 = desc ? mn : mx;
        }
    }
    sm[2*t] = e0; sm[2*t+1] = e1;
    __syncthreads();
}

// ---------------------------------------------------------------- cutoff helper for fallback (4096 bins)
__device__ void find_cutoff_4096(int* hist, int* part, int K, int* c_out){
    int tid = threadIdx.x;
    int p = 0;
    #pragma unroll
    for (int k = 0; k < 8; k++) p += hist[tid*8 + k];
    part[tid] = p;
    __syncthreads();
    for (int off = 1; off < 512; off <<= 1){
        int v = part[tid];
        if (tid + off < 512) v += part[tid + off];
        __syncthreads();
        part[tid] = v;
        __syncthreads();
    }
    if (tid == 0 && part[0] < K) *c_out = 0;
    if (part[tid] >= K && (tid == 511 || part[tid+1] < K)){
        int cum = (tid == 511) ? 0 : part[tid+1];
        for (int bn = tid*8 + 7; bn >= tid*8; bn--){
            cum += hist[bn];
            if (cum >= K){ *c_out = bn; break; }
        }
    }
    __syncthreads();
}

// ================================================================ kernel 2: per (image,class) NMS
__global__ __launch_bounds__(512) void nms_kernel(const float* __restrict__ y,
                                                  const float* __restrict__ bbox,
                                                  const float* __restrict__ anch){
    __shared__ __align__(16) unsigned char arena[32768];  // sbuf/hist -> masksT
    __shared__ float4 sboxes[KPERF];
    __shared__ float  svals[KPERF];
    __shared__ int    saidx[KPERF];
    __shared__ u32 keptw[16], validw[16];
    __shared__ int wpref[16];
    __shared__ int sn, scnt, sc1;

    int tid = threadIdx.x;
    int t = blockIdx.x;
    int b = t / NCLS, clsr = t % NCLS;
    const float4* bbox4 = reinterpret_cast<const float4*>(bbox);
    const float4* anch4 = reinterpret_cast<const float4*>(anch);

    for (int kk = tid; kk < KEEPC; kk += 512) g_fval[t*KEEPC + kk] = -1.0f;

    if (tid == 0){ sn = g_cnt[t]; g_cnt[t] = 0; }   // read + re-zero for next replay
    __syncthreads();
    int n = sn;
    u64* sbuf = (u64*)arena;

    if (n >= KPERF && n <= 1024){
        // ---- fast path: hybrid register sort of 1024
        u64 e0 = (2*tid     < n) ? g_cand[(size_t)t*CAP + 2*tid]     : 0ull;
        u64 e1 = (2*tid + 1 < n) ? g_cand[(size_t)t*CAP + 2*tid + 1] : 0ull;
        hybrid_sort_1024(sbuf, e0, e1);
    } else if (n > 1024 && n <= CAP){
        // ---- rare: 1024 < n <= 2048, classic smem sort
        #pragma unroll 4
        for (int i = tid; i < CAP; i += 512)
            sbuf[i] = (i < n) ? g_cand[(size_t)t*CAP + i] : 0ull;
        __syncthreads();
        bitonic_sort_desc(sbuf, CAP);
    } else {
        // ---- exact fallback: histogram-select from the raw column
        int c = clsr + 1;
        const float* col = y + (size_t)b*NA*NC + c;
        int* hist = (int*)arena;                 // 4096 ints
        int* part = (int*)(arena + 16384);       // 512 ints
        for (int i = tid; i < 4096; i += 512) hist[i] = 0;
        __syncthreads();
        for (int a = tid; a < NA; a += 512){
            float v = col[(size_t)a*NC];
            if (v > SCORE_THR){
                int bn = (int)(v*4096.f); bn = bn > 4095 ? 4095 : bn;
                atomicAdd(&hist[bn], 1);
            }
        }
        __syncthreads();
        find_cutoff_4096(hist, part, KPERF, &sc1);
        int c1 = sc1;
        if (tid == 0) scnt = 0;
        __syncthreads();                         // hist dead; reuse arena as sbuf
        for (int a = tid; a < NA; a += 512){
            float v = col[(size_t)a*NC];
            if (v > SCORE_THR){
                int bn = (int)(v*4096.f); bn = bn > 4095 ? 4095 : bn;
                if (bn >= c1){
                    int pos = atomicAdd(&scnt, 1);
                    if (pos < CAP)
                        sbuf[pos] = ((u64)fmono(v) << 32) | (u64)(0xFFFFFFFFu - (u32)a);
                }
            }
        }
        __syncthreads();
        int m = min(scnt, CAP);
        int n2 = 512;
        while (n2 < m) n2 <<= 1;
        for (int i = m + tid; i < n2; i += 512) sbuf[i] = 0ull;
        __syncthreads();
        bitonic_sort_desc(sbuf, n2);
    }

    // ---- extract top-500 + lazy box decode
    bool valid = false;
    if (tid < KPERF){
        u64 key = sbuf[tid];
        u32 mk = (u32)(key >> 32);
        if (mk > 0x80000000u){
            float v = fmono_inv(mk);
            int a = (int)(0xFFFFFFFFu - (u32)key);
            svals[tid] = v; saidx[tid] = a;
            sboxes[tid] = decode_box(bbox4[(size_t)b*NA + a], anch4[a]);
            valid = (v > 0.0f);
        } else {
            svals[tid] = -1.0f; saidx[tid] = 0;
            sboxes[tid] = make_float4(0.f, 0.f, 0.f, 0.f);
        }
    }
    {
        u32 bal = __ballot_sync(0xFFFFFFFFu, valid);
        if ((tid & 31) == 0) validw[tid >> 5] = bal;
    }
    __syncthreads();   // sbuf reads done; arena reused as masksT

    // ---- transposed suppression masks via warp-per-row ballot (balanced)
    u32* masksT = (u32*)arena;    // masksT[r*16 + w] = bits of j<r with IOU(r,j)>0.5
    int wid = tid >> 5, lane = tid & 31;
    for (int r = wid; r < KPERF; r += 16){
        float4 bi = sboxes[r];
        float areai = (bi.z - bi.x)*(bi.w - bi.y);
        int wmax = r >> 5;
        for (int w = 0; w <= wmax; w++){
            int j = w*32 + lane;
            bool o = false;
            if (j < r){
                float4 bj = sboxes[j];
                float lx = fmaxf(bi.x, bj.x), ly = fmaxf(bi.y, bj.y);
                float rx = fminf(bi.z, bj.z), ry = fminf(bi.w, bj.w);
                float iw = fmaxf(rx - lx, 0.f), ih = fmaxf(ry - ly, 0.f);
                float inter = iw*ih;
                float uni = areai + (bj.z - bj.x)*(bj.w - bj.y) - inter;
                o = inter > 0.5f*fmaxf(uni, 1e-9f);   // iou > 0.5
            }
            u32 bits = __ballot_sync(0xFFFFFFFFu, o);
            if (lane == 0) masksT[r*16 + w] = bits;
        }
        if (lane > wmax && lane < 16) masksT[r*16 + lane] = 0u;  // zero for backstop
    }
    if (tid < 16) keptw[tid] = validw[tid];
    __syncthreads();

    // ---- antitone fixed point (any fixed point == greedy NMS; convergence certified)
    bool converged = false;
    bool vld = (tid < KPERF) ? (svals[tid] > 0.0f) : false;
    for (int it = 0; it < 16; it++){
        bool supp = false;
        if (tid < KPERF){
            int w0 = tid >> 5;
            const u32* row = masksT + tid*16;
            for (int w = 0; w <= w0; w++) supp |= (keptw[w] & row[w]) != 0u;
        }
        bool nk = vld && !supp;
        u32 nb = __ballot_sync(0xFFFFFFFFu, nk);
        int ch = 0;
        if ((tid & 31) == 0 && nb != keptw[tid >> 5]){ keptw[tid >> 5] = nb; ch = 1; }
        if (__syncthreads_or(ch) == 0){ converged = true; break; }
    }
    if (!converged){
        if (tid < 32){       // exact serial backstop
            u32 kw = 0;
            for (int i = 0; i < KPERF; i++){
                u32 m = (tid < 16) ? masksT[i*16 + tid] : 0u;
                bool supp = __any_sync(0xFFFFFFFFu, (m & kw) != 0u);
                bool vi = svals[i] > 0.0f;
                if (vi && !supp && tid == (i >> 5)) kw |= 1u << (i & 31);
            }
            if (tid < 16) keptw[tid] = kw;
        }
        __syncthreads();
    }

    if (tid == 0){
        int acc = 0;
        #pragma unroll
        for (int w = 0; w < 16; w++){ wpref[w] = acc; acc += __popc(keptw[w]); }
    }
    __syncthreads();

    // ---- compact first KEEPC kept entries
    if (tid < KPERF){
        int w = tid >> 5, b2 = tid & 31;
        if ((keptw[w] >> b2) & 1u){
            int rank = wpref[w] + __popc(keptw[w] & ((1u << b2) - 1u));
            if (rank < KEEPC){
                g_fval [t*KEEPC + rank] = svals[tid];
                g_fflat[t*KEEPC + rank] = clsr*KPERF + tid;
                g_faidx[t*KEEPC + rank] = saidx[tid];
            }
        }
    }
}

// ---------------------------------------------------------------- final binning helpers
// level-1 bins remapped onto [0.99, 1] (all fast-path values are > 0.992)
__device__ __forceinline__ int bin1(float v){
    float t = (v - 0.99f)*409600.0f;
    int b = (int)t;
    return b < 0 ? 0 : (b > 4095 ? 4095 : b);
}
__device__ __forceinline__ int bin2(float v, int c1){
    if (c1 > 0){
        float t = (v - 0.99f)*409600.0f - (float)c1;   // frac within bin c1, monotone
        int s = (int)(t*4096.0f);
        return s < 0 ? 0 : (s > 4095 ? 4095 : s);
    } else {
        int s = (int)(v*4096.0f);
        return s < 0 ? 0 : (s > 4095 ? 4095 : s);
    }
}

// ================================================================ kernel 3: per-image global top-100 + gather
__global__ __launch_bounds__(512) void final_kernel(const float* __restrict__ y_pred,
                                                    const float* __restrict__ bbox,
                                                    const float* __restrict__ anch,
                                                    float* __restrict__ out){
    __shared__ int hist[4096];
    __shared__ int wt[16];
    __shared__ int sc, sab, sbin, sc2, scnt;
    __shared__ u64 skey[1024];
    __shared__ int sA[KPROP];
    int tid = threadIdx.x;
    int lane = tid & 31, wrp = tid >> 5;
    int b = blockIdx.x;
    const int gbase = b*MFIN;
    const float4* bbox4 = reinterpret_cast<const float4*>(bbox);
    const float4* anch4 = reinterpret_cast<const float4*>(anch);

    // ---- stage values into registers (independent loads)
    float vreg[RPT];
    #pragma unroll
    for (int k = 0; k < RPT; k++){
        int idx = tid + k*512;
        vreg[k] = (idx < MFIN) ? g_fval[gbase + idx] : -1.0f;
    }

    // ---- level-1 histogram
    for (int i = tid; i < 4096; i += 512) hist[i] = 0;
    __syncthreads();
    #pragma unroll
    for (int k = 0; k < RPT; k++){
        float v = vreg[k];
        if (v > 0.f) atomicAdd(&hist[bin1(v)], 1);
    }
    __syncthreads();

    // ---- level-1 cutoff via warp suffix scan (also record cutoff-bin count)
    {
        int p = 0;
        #pragma unroll
        for (int k = 0; k < 8; k++) p += hist[tid*8 + k];
        int s = p;
        #pragma unroll
        for (int off = 1; off < 32; off <<= 1){
            int v = __shfl_down_sync(0xFFFFFFFFu, s, off);
            if (lane + off < 32) s += v;
        }
        if (lane == 0) wt[wrp] = s;
        __syncthreads();
        int wsuf = 0;
        #pragma unroll
        for (int j = 0; j < 16; j++) if (j > wrp) wsuf += wt[j];
        int St = s + wsuf;
        if (tid == 0 && St < KPROP){ sc = 0; sab = 0; sbin = 0; }
        if (St >= KPROP && St - p < KPROP){
            int cum = St - p;
            for (int bn = tid*8 + 7; bn >= tid*8; bn--){
                cum += hist[bn];
                if (cum >= KPROP){ sc = bn; sab = cum - hist[bn]; sbin = hist[bn]; break; }
            }
        }
        __syncthreads();
    }
    int c1 = sc, ab1 = sab;
    int c2 = 0;
    bool need2 = (ab1 + sbin > 512);

    if (need2){
        // ---- level-2 refinement inside cutoff bin
        for (int i = tid; i < 4096; i += 512) hist[i] = 0;
        __syncthreads();
        #pragma unroll
        for (int k = 0; k < RPT; k++){
            float v = vreg[k];
            if (v > 0.f && bin1(v) == c1) atomicAdd(&hist[bin2(v, c1)], 1);
        }
        __syncthreads();
        int K2 = KPROP - ab1;
        int p = 0;
        #pragma unroll
        for (int k = 0; k < 8; k++) p += hist[tid*8 + k];
        int s = p;
        #pragma unroll
        for (int off = 1; off < 32; off <<= 1){
            int v = __shfl_down_sync(0xFFFFFFFFu, s, off);
            if (lane + off < 32) s += v;
        }
        if (lane == 0) wt[wrp] = s;
        __syncthreads();
        int wsuf = 0;
        #pragma unroll
        for (int j = 0; j < 16; j++) if (j > wrp) wsuf += wt[j];
        int St = s + wsuf;
        if (tid == 0 && St < K2) sc2 = 0;
        if (St >= K2 && St - p < K2){
            int cum = St - p;
            for (int bn = tid*8 + 7; bn >= tid*8; bn--){
                cum += hist[bn];
                if (cum >= K2){ sc2 = bn; break; }
            }
        }
        __syncthreads();
        c2 = sc2;
    }

    // ---- gather survivors
    if (tid == 0) scnt = 0;
    __syncthreads();
    #pragma unroll
    for (int k = 0; k < RPT; k++){
        float v = vreg[k];
        if (v > 0.f){
            int bn = bin1(v);
            bool sel = bn > c1;
            if (bn == c1) sel = !need2 || (bin2(v, c1) >= c2);
            if (sel){
                int i = tid + k*512;
                int pos = atomicAdd(&scnt, 1);
                if (pos < 512){
                    u32 fflat = (u32)g_fflat[gbase + i];
                    skey[pos] = ((u64)fmono(v) << 32) | ((u64)(65535u - fflat) << 14) | (u64)i;
                }
            }
        }
    }
    __syncthreads();
    int n = min(scnt, 512);
    for (int i = n + tid; i < 1024; i += 512) skey[i] = 0ull;
    __syncthreads();

    // ---- exact sort (hybrid 1024; upper half zeros)
    {
        u64 e0 = skey[2*tid], e1 = skey[2*tid + 1];
        hybrid_sort_1024(skey, e0, e1);
    }

    if (tid < KPROP){
        u64 key = skey[tid];
        u32 mk = (u32)(key >> 32);
        if (mk > 0x80000000u){
            int slot = (int)(key & 0x3FFFull);
            sA[tid] = g_faidx[gbase + slot];
        } else sA[tid] = -1;
    }
    __syncthreads();

    float* oscores = out;                         // [B,PROP,C]
    float* oboxes  = out + NB*KPROP*NC;           // [B,PROP,4]
    for (int idx = tid; idx < KPROP*NC; idx += 512){
        int p = idx / NC, cc = idx % NC;
        int a = sA[p];
        oscores[(b*KPROP + p)*NC + cc] = (a >= 0) ? y_pred[((size_t)b*NA + a)*NC + cc] : 0.f;
    }
    if (tid < KPROP){
        int a = sA[tid];
        float4 bx = make_float4(0.f, 0.f, 0.f, 0.f);
        if (a >= 0) bx = decode_box(bbox4[(size_t)b*NA + a], anch4[a]);
        reinterpret_cast<float4*>(oboxes)[b*KPROP + tid] = bx;
    }
}

// ----------------------------------------------------------------
extern "C" void kernel_launch(void* const* d_in, const int* in_sizes, int n_in,
                              void* d_out, int out_size){
    (void)in_sizes; (void)n_in; (void)out_size;
    const float* y    = (const float*)d_in[0];   // [B,A,C]
    const float* bbox = (const float*)d_in[1];   // [B,A,4]
    const float* anch = (const float*)d_in[2];   // [A,4]
    float* out = (float*)d_out;

    collect_kernel<<<dim3(NSLAB, NB), 640>>>(y);
    nms_kernel<<<NTASK, 512>>>(y, bbox, anch);
    final_kernel<<<NB, 512>>>(y, bbox, anch, out);
}